// round 3
// baseline (speedup 1.0000x reference)
#include <cuda_runtime.h>

typedef unsigned long long ull;

#define SEQ   256
#define BSZ   2048
#define FDIM  5
#define HDIM  64
#define KAUX  8
#define NCOL  1280           // 256 (main gates) + 8*128 (aux gates)
#define BT    16             // batch rows per block
#define NTHR  640            // 20 warps: 2 row-groups x 320 col-quads
#define NBLK  (BSZ / BT)     // 128 blocks, 1 per SM

// ---------------- repacked weights (device globals; prep kernel fills) ------
__device__ __align__(16) float g_Ucat[HDIM * NCOL];   // [h][col] recurrent cat
__device__ __align__(16) float g_Wx[FDIM * NCOL];     // [f][col] input proj cat
__device__ __align__(16) float g_bcat[NCOL];          // bias cat
__device__ __align__(16) float g_W2[128 * 256];       // [h<64:Wih^T, h>=64:Whh^T][j]
__device__ __align__(16) float g_b2[256];             // b_ih + b_hh
__device__ __align__(16) float g_WattP[HDIM * HDIM];  // [g][2l+p]=Watt[l+32p][g]
__device__ __align__(16) float g_linW[HDIM];

// ---------------- f32x2 helpers (FFMA2 path, sm_100+) -----------------------
__device__ __forceinline__ void fma2(ull &d, ull a, ull b) {
    asm("fma.rn.f32x2 %0, %1, %2, %0;" : "+l"(d) : "l"(a), "l"(b));
}
__device__ __forceinline__ void upk(ull v, float &lo, float &hi) {
    asm("mov.b64 {%0,%1}, %2;" : "=f"(lo), "=f"(hi) : "l"(v));
}

// ---------------- fast activations (fp32, ~1e-6 error) ----------------------
__device__ __forceinline__ float fsig(float x) {
    float e = __expf(-x);
    return __fdividef(1.f, 1.f + e);
}
__device__ __forceinline__ float ftanh(float x) {
    return 2.f * fsig(2.f * x) - 1.f;
}
// unified sigmoid/tanh without divergence: one fsig either way
__device__ __forceinline__ float actv(float x, bool is_sig) {
    float s = fsig(is_sig ? x : 2.f * x);
    return is_sig ? s : 2.f * s - 1.f;
}

// ---------------- prep: repack weights --------------------------------------
__global__ void prep_kernel(const float *__restrict__ Wm, const float *__restrict__ Um,
                            const float *__restrict__ bm, const float *__restrict__ Wa,
                            const float *__restrict__ Ua, const float *__restrict__ ba,
                            const float *__restrict__ Watt, const float *__restrict__ Wih,
                            const float *__restrict__ Whh, const float *__restrict__ bih,
                            const float *__restrict__ bhh, const float *__restrict__ linW) {
    int i = blockIdx.x * blockDim.x + threadIdx.x;
    if (i < HDIM * NCOL) {
        int h = i / NCOL, col = i % NCOL;
        float v;
        if (col < 256) v = Um[h * 256 + col];
        else { int cc = col - 256; int k = cc >> 7, j = cc & 127; v = Ua[(k * HDIM + h) * 128 + j]; }
        g_Ucat[i] = v;
    }
    if (i < FDIM * NCOL) {
        int f = i / NCOL, col = i % NCOL;
        float v;
        if (col < 256) v = Wm[f * 256 + col];
        else { int cc = col - 256; int k = cc >> 7, j = cc & 127; v = Wa[(k * FDIM + f) * 128 + j]; }
        g_Wx[i] = v;
    }
    if (i < NCOL) g_bcat[i] = (i < 256) ? bm[i] : ba[i - 256];
    if (i < 128 * 256) {
        int h = i / 256, j = i % 256;
        g_W2[i] = (h < 64) ? Wih[j * 64 + h] : Whh[j * 64 + (h - 64)];
    }
    if (i < 256) g_b2[i] = bih[i] + bhh[i];
    if (i < HDIM * HDIM) {
        int g = i >> 6, q = i & 63, l = q >> 1, p = q & 1;
        g_WattP[i] = Watt[(l + 32 * p) * HDIM + g];
    }
    if (i < HDIM) g_linW[i] = linW[i];
}

// ---------------- smem layout (floats) --------------------------------------
#define SM_G    0                       // activated gates [16][1280]   20480
#define SM_G2   20480                   // activated lstm2 gates [16][256] 4096
#define SM_HD   24576                   // [16][128] dup f2: h1 | h2     4096
#define SM_CD   28672                   // [16][64]  dup f2: c1          2048
#define SM_XD   30720                   // [9][5][16] dup f2             1440
#define SM_WP   32160                   // WattP copy                    4096
#define SM_TOT  36256                   // 145024 bytes

__global__ void __launch_bounds__(NTHR, 1)
mi_kernel(const float *__restrict__ Y,
          const float *__restrict__ X1, const float *__restrict__ X2,
          const float *__restrict__ X3, const float *__restrict__ X4,
          const float *__restrict__ X5, const float *__restrict__ X6,
          const float *__restrict__ X7, const float *__restrict__ X8,
          const float *__restrict__ batt_p, const float *__restrict__ linb_p,
          float *__restrict__ out) {
    extern __shared__ float sm[];
    float *sG  = sm + SM_G;
    float *sG2 = sm + SM_G2;
    float *sHD = sm + SM_HD;
    float *sCD = sm + SM_CD;
    float *sXD = sm + SM_XD;
    float *sWP = sm + SM_WP;

    const int tid  = threadIdx.x;
    const int warp = tid >> 5, lane = tid & 31;
    const int rg = (tid >= 320) ? 1 : 0;   // row-group: rows rg*8 .. rg*8+7
    const int q  = tid - rg * 320;         // col-quad 0..319 (cols 4q..4q+3)
    const int b0 = blockIdx.x * BT;

    const float batt = *batt_p;
    const float linb = *linb_p;
    const float *xp[9] = {Y, X1, X2, X3, X4, X5, X6, X7, X8};

    // phase-1 quad metadata
    const int c0 = 4 * q;
    const bool p1_sig = (c0 < 256) ? ((c0 >> 6) < 3) : (((c0 - 256) & 127) < 64);
    const int xsrc = (c0 < 256) ? 0 : 1 + ((c0 - 256) >> 7);

    // phase-2 mapping (threads 0..255)
    const int rg2 = tid >> 6;              // 0..3 -> rows 4*rg2..4*rg2+3
    const int q2  = tid & 63;              // quad: cols 4*q2..4*q2+3
    const bool p2_sig = (((4 * q2) >> 6) != 2);

    // init: WattP copy, zero state
    for (int i = tid; i < HDIM * HDIM; i += NTHR) sWP[i] = g_WattP[i];
    for (int i = tid; i < BT * 128 * 2; i += NTHR) sHD[i] = 0.f;
    for (int i = tid; i < BT * 64 * 2; i += NTHR)  sCD[i] = 0.f;

    float c1a = 0.f, c1b = 0.f;   // phase-1 cell (lane, lane+32) of row `warp`
    float c2a = 0.f, c2b = 0.f;   // phase-2 cell

    // stage inputs for t=0 (pre-duplicated): x[(s,f,row)] pairs
    for (int j = tid; j < 9 * BT * FDIM; j += NTHR) {
        int s = j / (BT * FDIM), rem = j - s * (BT * FDIM);
        int row = rem / FDIM, f = rem - row * FDIM;
        float v = xp[s][(size_t)b0 * FDIM + rem];
        int o = ((s * FDIM + f) * BT + row) * 2;
        sXD[o] = v; sXD[o + 1] = v;
    }
    __syncthreads();

    for (int t = 0; t < SEQ; t++) {
        // ===== phase-1 GEMM: G = act(b + x@Wx + h1@Ucat), one quad/thread ====
        {
            ull acc[8][2];
            {
                ull b01 = *(const ull *)&g_bcat[c0];
                ull b23 = *(const ull *)&g_bcat[c0 + 2];
#pragma unroll
                for (int r = 0; r < 8; r++) { acc[r][0] = b01; acc[r][1] = b23; }
            }
            // x contribution (K=5)
            const float *xb = &sXD[(xsrc * FDIM) * BT * 2 + rg * 16];
#pragma unroll
            for (int f = 0; f < FDIM; f++) {
                ull w0 = *(const ull *)&g_Wx[f * NCOL + c0];
                ull w1 = *(const ull *)&g_Wx[f * NCOL + c0 + 2];
#pragma unroll
                for (int r = 0; r < 8; r++) {
                    ull xd = *(const ull *)&xb[f * BT * 2 + r * 2];
                    fma2(acc[r][0], xd, w0);
                    fma2(acc[r][1], xd, w1);
                }
            }
            // h contribution (K=64)
            const float *up = &g_Ucat[c0];
            const float *hb = &sHD[rg * 8 * 128 * 2];
#pragma unroll 2
            for (int h = 0; h < HDIM; h++) {
                ull w0 = *(const ull *)(up);
                ull w1 = *(const ull *)(up + 2);
                up += NCOL;
#pragma unroll
                for (int r = 0; r < 8; r++) {
                    ull hd = *(const ull *)&hb[(r * 128 + h) * 2];
                    fma2(acc[r][0], hd, w0);
                    fma2(acc[r][1], hd, w1);
                }
            }
            // epilogue: activate + store quad
#pragma unroll
            for (int r = 0; r < 8; r++) {
                float a0, a1, a2, a3;
                upk(acc[r][0], a0, a1);
                upk(acc[r][1], a2, a3);
                float4 v;
                v.x = actv(a0, p1_sig); v.y = actv(a1, p1_sig);
                v.z = actv(a2, p1_sig); v.w = actv(a3, p1_sig);
                *(float4 *)&sG[(rg * 8 + r) * NCOL + c0] = v;
            }
        }
        __syncthreads();

        // ========== phase-1 attention + state update (warp r = row r) ========
        if (warp < BT) {
            const int r = warp;
            const float *Gr = &sG[r * NCOL];
            const int h0 = lane, h1 = lane + 32;

            float fa0 = Gr[64 + h0], fa1 = Gr[64 + h1];
            float oa0 = Gr[128 + h0], oa1 = Gr[128 + h1];

            float l0[9], l1[9];
            l0[0] = Gr[h0] * Gr[192 + h0];
            l1[0] = Gr[h1] * Gr[192 + h1];
#pragma unroll
            for (int k = 0; k < KAUX; k++) {
                const float *Ga = Gr + 256 + 128 * k;
                l0[k + 1] = Ga[h0] * Ga[64 + h0];
                l1[k + 1] = Ga[h1] * Ga[64 + h1];
            }

            // v = W_att @ c_prev  (FFMA2: dup'd c x paired W_att)
            ull vacc = 0ull;
#pragma unroll 8
            for (int g = 0; g < HDIM; g++)
                fma2(vacc, *(const ull *)&sCD[(r * HDIM + g) * 2],
                           *(const ull *)&sWP[g * HDIM + 2 * lane]);
            float v0, v1; upk(vacc, v0, v1);

            float e[9], esum = 0.f;
#pragma unroll
            for (int k = 0; k < 9; k++) {
                float d = l0[k] * v0 + l1[k] * v1;
                d += __shfl_xor_sync(0xffffffffu, d, 16);
                d += __shfl_xor_sync(0xffffffffu, d, 8);
                d += __shfl_xor_sync(0xffffffffu, d, 4);
                d += __shfl_xor_sync(0xffffffffu, d, 2);
                d += __shfl_xor_sync(0xffffffffu, d, 1);
                e[k] = __expf(ftanh(d + batt));
                esum += e[k];
            }
            float inv = __fdividef(1.f, esum);
            float L0 = 0.f, L1 = 0.f;
#pragma unroll
            for (int k = 0; k < 9; k++) {
                float a = e[k] * inv;
                L0 = fmaf(a, l0[k], L0);
                L1 = fmaf(a, l1[k], L1);
            }
            float cn0 = fmaf(fa0, c1a, L0), cn1 = fmaf(fa1, c1b, L1);
            float hn0 = oa0 * ftanh(cn0),   hn1 = oa1 * ftanh(cn1);
            c1a = cn0; c1b = cn1;
            __syncwarp();                            // matvec reads of sCD done
            int oc0 = (r * HDIM + h0) * 2, oc1 = (r * HDIM + h1) * 2;
            sCD[oc0] = cn0; sCD[oc0 + 1] = cn0;
            sCD[oc1] = cn1; sCD[oc1 + 1] = cn1;
            int oh0 = (r * 128 + h0) * 2, oh1 = (r * 128 + h1) * 2;
            sHD[oh0] = hn0; sHD[oh0 + 1] = hn0;
            sHD[oh1] = hn1; sHD[oh1 + 1] = hn1;
        }
        __syncthreads();

        // ===== phase-2 GEMM (threads 0..255) + x(t+1) prefetch (512..639) ====
        if (tid < 256) {
            ull acc2[4][2];
            {
                ull b01 = *(const ull *)&g_b2[4 * q2];
                ull b23 = *(const ull *)&g_b2[4 * q2 + 2];
#pragma unroll
                for (int r = 0; r < 4; r++) { acc2[r][0] = b01; acc2[r][1] = b23; }
            }
            const float *wp = &g_W2[4 * q2];
            const float *hb = &sHD[rg2 * 4 * 128 * 2];
#pragma unroll 2
            for (int h = 0; h < 128; h++) {
                ull w0 = *(const ull *)(wp);
                ull w1 = *(const ull *)(wp + 2);
                wp += 256;
#pragma unroll
                for (int r = 0; r < 4; r++) {
                    ull hd = *(const ull *)&hb[(r * 128 + h) * 2];
                    fma2(acc2[r][0], hd, w0);
                    fma2(acc2[r][1], hd, w1);
                }
            }
#pragma unroll
            for (int r = 0; r < 4; r++) {
                float a0, a1, a2, a3;
                upk(acc2[r][0], a0, a1);
                upk(acc2[r][1], a2, a3);
                float4 v;
                v.x = actv(a0, p2_sig); v.y = actv(a1, p2_sig);
                v.z = actv(a2, p2_sig); v.w = actv(a3, p2_sig);
                *(float4 *)&sG2[(rg2 * 4 + r) * 256 + 4 * q2] = v;
            }
        } else if (tid >= 512 && t + 1 < SEQ) {
            // prefetch + stage x(t+1); safe: sXD reads happened in phase-1
            size_t base = (size_t)(t + 1) * BSZ * FDIM + (size_t)b0 * FDIM;
            for (int j = tid - 512; j < 9 * BT * FDIM; j += 128) {
                int s = j / (BT * FDIM), rem = j - s * (BT * FDIM);
                int row = rem / FDIM, f = rem - row * FDIM;
                float v = xp[s][base + rem];
                int o = ((s * FDIM + f) * BT + row) * 2;
                sXD[o] = v; sXD[o + 1] = v;
            }
        }
        __syncthreads();

        // ================= phase-2 state update + output head ================
        if (warp < BT) {
            const int r = warp;
            const float *gr = &sG2[r * 256];
            const int j0 = lane, j1 = lane + 32;
            float ia0 = gr[j0],        ia1 = gr[j1];
            float fa0 = gr[64 + j0],   fa1 = gr[64 + j1];
            float ga0 = gr[128 + j0],  ga1 = gr[128 + j1];
            float oa0 = gr[192 + j0],  oa1 = gr[192 + j1];
            c2a = fmaf(fa0, c2a, ia0 * ga0);
            c2b = fmaf(fa1, c2b, ia1 * ga1);
            float h20 = oa0 * ftanh(c2a), h21 = oa1 * ftanh(c2b);
            int o0i = (r * 128 + 64 + j0) * 2, o1i = (r * 128 + 64 + j1) * 2;
            sHD[o0i] = h20; sHD[o0i + 1] = h20;
            sHD[o1i] = h21; sHD[o1i + 1] = h21;
            float ov = fmaxf(h20, 0.f) * g_linW[j0] + fmaxf(h21, 0.f) * g_linW[j1];
            ov += __shfl_xor_sync(0xffffffffu, ov, 16);
            ov += __shfl_xor_sync(0xffffffffu, ov, 8);
            ov += __shfl_xor_sync(0xffffffffu, ov, 4);
            ov += __shfl_xor_sync(0xffffffffu, ov, 2);
            ov += __shfl_xor_sync(0xffffffffu, ov, 1);
            if (lane == 0) out[(size_t)t * BSZ + b0 + r] = ov + linb;
        }
        __syncthreads();
    }
}

// ---------------- launch ----------------------------------------------------
extern "C" void kernel_launch(void *const *d_in, const int *in_sizes, int n_in,
                              void *d_out, int out_size) {
    (void)in_sizes; (void)n_in; (void)out_size;
    const float *Y    = (const float *)d_in[0];
    const float *x1   = (const float *)d_in[1];
    const float *x2   = (const float *)d_in[2];
    const float *x3   = (const float *)d_in[3];
    const float *x4   = (const float *)d_in[4];
    const float *x5   = (const float *)d_in[5];
    const float *x6   = (const float *)d_in[6];
    const float *x7   = (const float *)d_in[7];
    const float *x8   = (const float *)d_in[8];
    const float *Wm   = (const float *)d_in[9];
    const float *Um   = (const float *)d_in[10];
    const float *bm   = (const float *)d_in[11];
    const float *Wa   = (const float *)d_in[12];
    const float *Ua   = (const float *)d_in[13];
    const float *ba   = (const float *)d_in[14];
    const float *Watt = (const float *)d_in[15];
    const float *batt = (const float *)d_in[16];
    const float *Wih  = (const float *)d_in[17];
    const float *Whh  = (const float *)d_in[18];
    const float *bih  = (const float *)d_in[19];
    const float *bhh  = (const float *)d_in[20];
    const float *linW = (const float *)d_in[21];
    const float *linb = (const float *)d_in[22];
    float *out = (float *)d_out;

    prep_kernel<<<(HDIM * NCOL + 255) / 256, 256>>>(Wm, Um, bm, Wa, Ua, ba, Watt,
                                                    Wih, Whh, bih, bhh, linW);

    cudaFuncSetAttribute(mi_kernel, cudaFuncAttributeMaxDynamicSharedMemorySize,
                         SM_TOT * (int)sizeof(float));
    mi_kernel<<<NBLK, NTHR, SM_TOT * sizeof(float)>>>(Y, x1, x2, x3, x4, x5, x6, x7, x8,
                                                      batt, linb, out);
}

// round 4
// speedup vs baseline: 1.0403x; 1.0403x over previous
#include <cuda_runtime.h>

typedef unsigned long long ull;

#define SEQ   256
#define BSZ   2048
#define FDIM  5
#define HDIM  64
#define KAUX  8
#define NCOL  1280           // 256 (main gates) + 8*128 (aux gates)
#define BT    16             // batch rows per block
#define NTHR  640            // 20 warps: 2 row-groups x 320 col-quads
#define NBLK  (BSZ / BT)     // 128 blocks, 1 per SM

// ---------------- repacked weights (device globals; prep kernel fills) ------
__device__ __align__(16) float g_Ucat[HDIM * NCOL];   // [h][col] recurrent cat
__device__ __align__(16) float g_Wx[FDIM * NCOL];     // [f][col] input proj cat
__device__ __align__(16) float g_bcat[NCOL];          // bias cat
__device__ __align__(16) float g_W2[128 * 256];       // [h<64:Wih^T, h>=64:Whh^T][j]
__device__ __align__(16) float g_b2[256];             // b_ih + b_hh
__device__ __align__(16) float g_WattP[HDIM * HDIM];  // [g][2l+p]=Watt[l+32p][g]
__device__ __align__(16) float g_linW[HDIM];

// ---------------- f32x2 helpers (FFMA2 path, sm_100+) -----------------------
__device__ __forceinline__ void fma2(ull &d, ull a, ull b) {
    asm("fma.rn.f32x2 %0, %1, %2, %0;" : "+l"(d) : "l"(a), "l"(b));
}
__device__ __forceinline__ void upk(ull v, float &lo, float &hi) {
    asm("mov.b64 {%0,%1}, %2;" : "=f"(lo), "=f"(hi) : "l"(v));
}

// ---------------- fast activations (fp32, ~1e-6 error) ----------------------
__device__ __forceinline__ float fsig(float x) {
    float e = __expf(-x);
    return __fdividef(1.f, 1.f + e);
}
__device__ __forceinline__ float ftanh(float x) {
    return 2.f * fsig(2.f * x) - 1.f;
}
// unified sigmoid/tanh without divergence: one fsig either way
__device__ __forceinline__ float actv(float x, bool is_sig) {
    float s = fsig(is_sig ? x : 2.f * x);
    return is_sig ? s : 2.f * s - 1.f;
}

// ---------------- prep: repack weights --------------------------------------
__global__ void prep_kernel(const float *__restrict__ Wm, const float *__restrict__ Um,
                            const float *__restrict__ bm, const float *__restrict__ Wa,
                            const float *__restrict__ Ua, const float *__restrict__ ba,
                            const float *__restrict__ Watt, const float *__restrict__ Wih,
                            const float *__restrict__ Whh, const float *__restrict__ bih,
                            const float *__restrict__ bhh, const float *__restrict__ linW) {
    int i = blockIdx.x * blockDim.x + threadIdx.x;
    if (i < HDIM * NCOL) {
        int h = i / NCOL, col = i % NCOL;
        float v;
        if (col < 256) v = Um[h * 256 + col];
        else { int cc = col - 256; int k = cc >> 7, j = cc & 127; v = Ua[(k * HDIM + h) * 128 + j]; }
        g_Ucat[i] = v;
    }
    if (i < FDIM * NCOL) {
        int f = i / NCOL, col = i % NCOL;
        float v;
        if (col < 256) v = Wm[f * 256 + col];
        else { int cc = col - 256; int k = cc >> 7, j = cc & 127; v = Wa[(k * FDIM + f) * 128 + j]; }
        g_Wx[i] = v;
    }
    if (i < NCOL) g_bcat[i] = (i < 256) ? bm[i] : ba[i - 256];
    if (i < 128 * 256) {
        int h = i / 256, j = i % 256;
        g_W2[i] = (h < 64) ? Wih[j * 64 + h] : Whh[j * 64 + (h - 64)];
    }
    if (i < 256) g_b2[i] = bih[i] + bhh[i];
    if (i < HDIM * HDIM) {
        int g = i >> 6, q = i & 63, l = q >> 1, p = q & 1;
        g_WattP[i] = Watt[(l + 32 * p) * HDIM + g];
    }
    if (i < HDIM) g_linW[i] = linW[i];
}

// ---------------- smem layout (floats) --------------------------------------
#define SM_G    0                       // activated gates [16][1280]   20480
#define SM_G2   20480                   // activated lstm2 gates [16][256] 4096
#define SM_HD   24576                   // [16][128] dup f2: h1 | h2     4096
#define SM_CD   28672                   // [16][64]  dup f2: c1          2048
#define SM_XD   30720                   // [9][5][16] dup f2             1440
#define SM_WP   32160                   // WattP copy                    4096
#define SM_TOT  36256                   // 145024 bytes

__global__ void __launch_bounds__(NTHR, 1)
mi_kernel(const float *__restrict__ Y,
          const float *__restrict__ X1, const float *__restrict__ X2,
          const float *__restrict__ X3, const float *__restrict__ X4,
          const float *__restrict__ X5, const float *__restrict__ X6,
          const float *__restrict__ X7, const float *__restrict__ X8,
          const float *__restrict__ batt_p, const float *__restrict__ linb_p,
          float *__restrict__ out) {
    extern __shared__ float sm[];
    float *sG  = sm + SM_G;
    float *sG2 = sm + SM_G2;
    float *sHD = sm + SM_HD;
    float *sCD = sm + SM_CD;
    float *sXD = sm + SM_XD;
    float *sWP = sm + SM_WP;

    const int tid  = threadIdx.x;
    const int warp = tid >> 5, lane = tid & 31;
    const int rg = (tid >= 320) ? 1 : 0;   // row-group: rows rg*8 .. rg*8+7
    const int q  = tid - rg * 320;         // col-quad 0..319 (cols 4q..4q+3)
    const int b0 = blockIdx.x * BT;

    const float batt = *batt_p;
    const float linb = *linb_p;
    const float *xp[9] = {Y, X1, X2, X3, X4, X5, X6, X7, X8};

    // phase-1 quad metadata
    const int c0 = 4 * q;
    const bool p1_sig = (c0 < 256) ? ((c0 >> 6) < 3) : (((c0 - 256) & 127) < 64);
    const int xsrc = (c0 < 256) ? 0 : 1 + ((c0 - 256) >> 7);

    // phase-2 mapping (threads 0..255)
    const int rg2 = tid >> 6;              // 0..3 -> rows 4*rg2..4*rg2+3
    const int q2  = tid & 63;              // quad: cols 4*q2..4*q2+3
    const bool p2_sig = (((4 * q2) >> 6) != 2);

    // init: WattP copy, zero state
    for (int i = tid; i < HDIM * HDIM; i += NTHR) sWP[i] = g_WattP[i];
    for (int i = tid; i < BT * 128 * 2; i += NTHR) sHD[i] = 0.f;
    for (int i = tid; i < BT * 64 * 2; i += NTHR)  sCD[i] = 0.f;

    float c1a = 0.f, c1b = 0.f;   // phase-1 cell (lane, lane+32) of row `warp`
    float c2a = 0.f, c2b = 0.f;   // phase-2 cell

    // stage inputs for t=0 (pre-duplicated): x[(s,f,row)] pairs
    for (int j = tid; j < 9 * BT * FDIM; j += NTHR) {
        int s = j / (BT * FDIM), rem = j - s * (BT * FDIM);
        int row = rem / FDIM, f = rem - row * FDIM;
        float v = xp[s][(size_t)b0 * FDIM + rem];
        int o = ((s * FDIM + f) * BT + row) * 2;
        sXD[o] = v; sXD[o + 1] = v;
    }
    __syncthreads();

    for (int t = 0; t < SEQ; t++) {
        // ===== phase-1 GEMM: G = act(b + x@Wx + h1@Ucat), one quad/thread ====
        {
            ull acc[8][2];
            {
                ull b01 = *(const ull *)&g_bcat[c0];
                ull b23 = *(const ull *)&g_bcat[c0 + 2];
#pragma unroll
                for (int r = 0; r < 8; r++) { acc[r][0] = b01; acc[r][1] = b23; }
            }
            // x contribution (K=5)
            const float *xb = &sXD[(xsrc * FDIM) * BT * 2 + rg * 16];
#pragma unroll
            for (int f = 0; f < FDIM; f++) {
                ull w0 = *(const ull *)&g_Wx[f * NCOL + c0];
                ull w1 = *(const ull *)&g_Wx[f * NCOL + c0 + 2];
#pragma unroll
                for (int r = 0; r < 8; r++) {
                    ull xd = *(const ull *)&xb[f * BT * 2 + r * 2];
                    fma2(acc[r][0], xd, w0);
                    fma2(acc[r][1], xd, w1);
                }
            }
            // h contribution (K=64)
            const float *up = &g_Ucat[c0];
            const float *hb = &sHD[rg * 8 * 128 * 2];
#pragma unroll 2
            for (int h = 0; h < HDIM; h++) {
                ull w0 = *(const ull *)(up);
                ull w1 = *(const ull *)(up + 2);
                up += NCOL;
#pragma unroll
                for (int r = 0; r < 8; r++) {
                    ull hd = *(const ull *)&hb[(r * 128 + h) * 2];
                    fma2(acc[r][0], hd, w0);
                    fma2(acc[r][1], hd, w1);
                }
            }
            // epilogue: activate + store quad
#pragma unroll
            for (int r = 0; r < 8; r++) {
                float a0, a1, a2, a3;
                upk(acc[r][0], a0, a1);
                upk(acc[r][1], a2, a3);
                float4 v;
                v.x = actv(a0, p1_sig); v.y = actv(a1, p1_sig);
                v.z = actv(a2, p1_sig); v.w = actv(a3, p1_sig);
                *(float4 *)&sG[(rg * 8 + r) * NCOL + c0] = v;
            }
        }
        __syncthreads();

        // ========== phase-1 attention + state update (warp r = row r) ========
        if (warp < BT) {
            const int r = warp;
            const float *Gr = &sG[r * NCOL];
            const int h0 = lane, h1 = lane + 32;

            float fa0 = Gr[64 + h0], fa1 = Gr[64 + h1];
            float oa0 = Gr[128 + h0], oa1 = Gr[128 + h1];

            float l0[9], l1[9];
            l0[0] = Gr[h0] * Gr[192 + h0];
            l1[0] = Gr[h1] * Gr[192 + h1];
#pragma unroll
            for (int k = 0; k < KAUX; k++) {
                const float *Ga = Gr + 256 + 128 * k;
                l0[k + 1] = Ga[h0] * Ga[64 + h0];
                l1[k + 1] = Ga[h1] * Ga[64 + h1];
            }

            // v = W_att @ c_prev  (FFMA2: dup'd c x paired W_att)
            ull vacc = 0ull;
#pragma unroll 8
            for (int g = 0; g < HDIM; g++)
                fma2(vacc, *(const ull *)&sCD[(r * HDIM + g) * 2],
                           *(const ull *)&sWP[g * HDIM + 2 * lane]);
            float v0, v1; upk(vacc, v0, v1);

            float e[9], esum = 0.f;
#pragma unroll
            for (int k = 0; k < 9; k++) {
                float d = l0[k] * v0 + l1[k] * v1;
                d += __shfl_xor_sync(0xffffffffu, d, 16);
                d += __shfl_xor_sync(0xffffffffu, d, 8);
                d += __shfl_xor_sync(0xffffffffu, d, 4);
                d += __shfl_xor_sync(0xffffffffu, d, 2);
                d += __shfl_xor_sync(0xffffffffu, d, 1);
                e[k] = __expf(ftanh(d + batt));
                esum += e[k];
            }
            float inv = __fdividef(1.f, esum);
            float L0 = 0.f, L1 = 0.f;
#pragma unroll
            for (int k = 0; k < 9; k++) {
                float a = e[k] * inv;
                L0 = fmaf(a, l0[k], L0);
                L1 = fmaf(a, l1[k], L1);
            }
            float cn0 = fmaf(fa0, c1a, L0), cn1 = fmaf(fa1, c1b, L1);
            float hn0 = oa0 * ftanh(cn0),   hn1 = oa1 * ftanh(cn1);
            c1a = cn0; c1b = cn1;
            __syncwarp();                            // matvec reads of sCD done
            int oc0 = (r * HDIM + h0) * 2, oc1 = (r * HDIM + h1) * 2;
            sCD[oc0] = cn0; sCD[oc0 + 1] = cn0;
            sCD[oc1] = cn1; sCD[oc1 + 1] = cn1;
            int oh0 = (r * 128 + h0) * 2, oh1 = (r * 128 + h1) * 2;
            sHD[oh0] = hn0; sHD[oh0 + 1] = hn0;
            sHD[oh1] = hn1; sHD[oh1 + 1] = hn1;
        }
        __syncthreads();

        // ===== phase-2 GEMM (threads 0..255) + x(t+1) prefetch (512..639) ====
        if (tid < 256) {
            ull acc2[4][2];
            {
                ull b01 = *(const ull *)&g_b2[4 * q2];
                ull b23 = *(const ull *)&g_b2[4 * q2 + 2];
#pragma unroll
                for (int r = 0; r < 4; r++) { acc2[r][0] = b01; acc2[r][1] = b23; }
            }
            const float *wp = &g_W2[4 * q2];
            const float *hb = &sHD[rg2 * 4 * 128 * 2];
#pragma unroll 2
            for (int h = 0; h < 128; h++) {
                ull w0 = *(const ull *)(wp);
                ull w1 = *(const ull *)(wp + 2);
                wp += 256;
#pragma unroll
                for (int r = 0; r < 4; r++) {
                    ull hd = *(const ull *)&hb[(r * 128 + h) * 2];
                    fma2(acc2[r][0], hd, w0);
                    fma2(acc2[r][1], hd, w1);
                }
            }
#pragma unroll
            for (int r = 0; r < 4; r++) {
                float a0, a1, a2, a3;
                upk(acc2[r][0], a0, a1);
                upk(acc2[r][1], a2, a3);
                float4 v;
                v.x = actv(a0, p2_sig); v.y = actv(a1, p2_sig);
                v.z = actv(a2, p2_sig); v.w = actv(a3, p2_sig);
                *(float4 *)&sG2[(rg2 * 4 + r) * 256 + 4 * q2] = v;
            }
        } else if (tid >= 512 && t + 1 < SEQ) {
            // prefetch + stage x(t+1); safe: sXD reads happened in phase-1
            size_t base = (size_t)(t + 1) * BSZ * FDIM + (size_t)b0 * FDIM;
            for (int j = tid - 512; j < 9 * BT * FDIM; j += 128) {
                int s = j / (BT * FDIM), rem = j - s * (BT * FDIM);
                int row = rem / FDIM, f = rem - row * FDIM;
                float v = xp[s][base + rem];
                int o = ((s * FDIM + f) * BT + row) * 2;
                sXD[o] = v; sXD[o + 1] = v;
            }
        }
        __syncthreads();

        // ================= phase-2 state update + output head ================
        if (warp < BT) {
            const int r = warp;
            const float *gr = &sG2[r * 256];
            const int j0 = lane, j1 = lane + 32;
            float ia0 = gr[j0],        ia1 = gr[j1];
            float fa0 = gr[64 + j0],   fa1 = gr[64 + j1];
            float ga0 = gr[128 + j0],  ga1 = gr[128 + j1];
            float oa0 = gr[192 + j0],  oa1 = gr[192 + j1];
            c2a = fmaf(fa0, c2a, ia0 * ga0);
            c2b = fmaf(fa1, c2b, ia1 * ga1);
            float h20 = oa0 * ftanh(c2a), h21 = oa1 * ftanh(c2b);
            int o0i = (r * 128 + 64 + j0) * 2, o1i = (r * 128 + 64 + j1) * 2;
            sHD[o0i] = h20; sHD[o0i + 1] = h20;
            sHD[o1i] = h21; sHD[o1i + 1] = h21;
            float ov = fmaxf(h20, 0.f) * g_linW[j0] + fmaxf(h21, 0.f) * g_linW[j1];
            ov += __shfl_xor_sync(0xffffffffu, ov, 16);
            ov += __shfl_xor_sync(0xffffffffu, ov, 8);
            ov += __shfl_xor_sync(0xffffffffu, ov, 4);
            ov += __shfl_xor_sync(0xffffffffu, ov, 2);
            ov += __shfl_xor_sync(0xffffffffu, ov, 1);
            if (lane == 0) out[(size_t)t * BSZ + b0 + r] = ov + linb;
        }
        __syncthreads();
    }
}

// ---------------- launch ----------------------------------------------------
extern "C" void kernel_launch(void *const *d_in, const int *in_sizes, int n_in,
                              void *d_out, int out_size) {
    (void)in_sizes; (void)n_in; (void)out_size;
    const float *Y    = (const float *)d_in[0];
    const float *x1   = (const float *)d_in[1];
    const float *x2   = (const float *)d_in[2];
    const float *x3   = (const float *)d_in[3];
    const float *x4   = (const float *)d_in[4];
    const float *x5   = (const float *)d_in[5];
    const float *x6   = (const float *)d_in[6];
    const float *x7   = (const float *)d_in[7];
    const float *x8   = (const float *)d_in[8];
    const float *Wm   = (const float *)d_in[9];
    const float *Um   = (const float *)d_in[10];
    const float *bm   = (const float *)d_in[11];
    const float *Wa   = (const float *)d_in[12];
    const float *Ua   = (const float *)d_in[13];
    const float *ba   = (const float *)d_in[14];
    const float *Watt = (const float *)d_in[15];
    const float *batt = (const float *)d_in[16];
    const float *Wih  = (const float *)d_in[17];
    const float *Whh  = (const float *)d_in[18];
    const float *bih  = (const float *)d_in[19];
    const float *bhh  = (const float *)d_in[20];
    const float *linW = (const float *)d_in[21];
    const float *linb = (const float *)d_in[22];
    float *out = (float *)d_out;

    prep_kernel<<<(HDIM * NCOL + 255) / 256, 256>>>(Wm, Um, bm, Wa, Ua, ba, Watt,
                                                    Wih, Whh, bih, bhh, linW);

    cudaFuncSetAttribute(mi_kernel, cudaFuncAttributeMaxDynamicSharedMemorySize,
                         SM_TOT * (int)sizeof(float));
    mi_kernel<<<NBLK, NTHR, SM_TOT * sizeof(float)>>>(Y, x1, x2, x3, x4, x5, x6, x7, x8,
                                                      batt, linb, out);
}